// round 10
// baseline (speedup 1.0000x reference)
#include <cuda_runtime.h>
#include <cstdint>

#define NN 10000     // nodes
#define FF 128       // feature dim
#define BT 4         // B*T
#define EE 160000    // edges
#define NLAYERS 2

// Persistent device scratch (no allocations in kernel_launch)
__device__ float g_h[(size_t)BT * NN * FF];     // hidden state between layers
__device__ float g_agg[(size_t)BT * NN * FF];   // h_neigh (pre-scaled by 1/deg)
__device__ int   g_degi[NN];
__device__ int   g_rowptr[NN + 1];
__device__ int   g_cursor[NN];
__device__ int   g_csr_src[EE];

typedef unsigned long long ull;

// ---------------------------------------------------------------------------
// CSR build
// ---------------------------------------------------------------------------
__global__ void zero_degi_kernel() {
    int i = blockIdx.x * blockDim.x + threadIdx.x;
    if (i < NN) g_degi[i] = 0;
}

__global__ void degi_kernel(const int* __restrict__ edge_dst) {
    int e = blockIdx.x * blockDim.x + threadIdx.x;
    if (e < EE) atomicAdd(&g_degi[edge_dst[e]], 1);
}

// Single-block exclusive prefix sum over degrees -> rowptr + cursor.
__global__ void prefix_kernel() {
    const int CH = 40;                      // 256*40 = 10240 >= NN
    __shared__ int s[256];
    int tid = threadIdx.x;
    int base = tid * CH;
    int local = 0;
    #pragma unroll
    for (int j = 0; j < CH; j++) {
        int idx = base + j;
        if (idx < NN) local += g_degi[idx];
    }
    s[tid] = local;
    __syncthreads();
    if (tid == 0) {
        int run = 0;
        for (int i = 0; i < 256; i++) { int t = s[i]; s[i] = run; run += t; }
    }
    __syncthreads();
    int off = s[tid];
    #pragma unroll
    for (int j = 0; j < CH; j++) {
        int idx = base + j;
        if (idx < NN) {
            g_rowptr[idx] = off;
            g_cursor[idx] = off;
            off += g_degi[idx];
        }
    }
    if (tid == 0) g_rowptr[NN] = EE;
}

__global__ void fill_kernel(const int* __restrict__ edge_src,
                            const int* __restrict__ edge_dst) {
    int e = blockIdx.x * blockDim.x + threadIdx.x;
    if (e < EE) {
        int d = edge_dst[e];
        int p = atomicAdd(&g_cursor[d], 1);
        g_csr_src[p] = edge_src[e];
    }
}

// ---------------------------------------------------------------------------
// Aggregation: one warp per dst node, all BT at once, register accumulation.
// g_agg = mean of neighbor rows (invdeg folded in). No atomics, no zeroing.
// ---------------------------------------------------------------------------
__global__ __launch_bounds__(256) void agg_kernel(const float* __restrict__ Xin,
                                                  int layer) {
    const float* __restrict__ X = (layer == 0) ? Xin : g_h;
    int w = (blockIdx.x * blockDim.x + threadIdx.x) >> 5;
    int lane = threadIdx.x & 31;
    if (w >= NN) return;

    int beg = g_rowptr[w];
    int end = g_rowptr[w + 1];
    float inv = (end > beg) ? 1.0f / (float)(end - beg) : 0.0f;

    float4 acc[BT];
    #pragma unroll
    for (int bt = 0; bt < BT; bt++) acc[bt] = make_float4(0.f, 0.f, 0.f, 0.f);

    int e = beg;
    for (; e + 1 < end; e += 2) {                 // 2 edges/iter for MLP
        int s0 = g_csr_src[e];
        int s1 = g_csr_src[e + 1];
        #pragma unroll
        for (int bt = 0; bt < BT; bt++) {
            float4 v0 = *reinterpret_cast<const float4*>(
                X + ((size_t)bt * NN + s0) * FF + lane * 4);
            float4 v1 = *reinterpret_cast<const float4*>(
                X + ((size_t)bt * NN + s1) * FF + lane * 4);
            acc[bt].x += v0.x + v1.x;
            acc[bt].y += v0.y + v1.y;
            acc[bt].z += v0.z + v1.z;
            acc[bt].w += v0.w + v1.w;
        }
    }
    if (e < end) {
        int s0 = g_csr_src[e];
        #pragma unroll
        for (int bt = 0; bt < BT; bt++) {
            float4 v0 = *reinterpret_cast<const float4*>(
                X + ((size_t)bt * NN + s0) * FF + lane * 4);
            acc[bt].x += v0.x; acc[bt].y += v0.y;
            acc[bt].z += v0.z; acc[bt].w += v0.w;
        }
    }
    #pragma unroll
    for (int bt = 0; bt < BT; bt++) {
        float4 o;
        o.x = acc[bt].x * inv; o.y = acc[bt].y * inv;
        o.z = acc[bt].z * inv; o.w = acc[bt].w * inv;
        *reinterpret_cast<float4*>(
            g_agg + ((size_t)bt * NN + w) * FF + lane * 4) = o;
    }
}

// ---------------------------------------------------------------------------
// Fused GEMM with packed f32x2 FMA (FFMA2, sm_103a):
//   Y = X*Ws + Agg*Wn + b
// Accumulators packed over row pairs (free: adjacent rows in k-major A tile
// are the two 32-bit halves of an ulonglong). W tiles stored DUPLICATED in
// shared so the broadcast operand is a plain 64-bit load: (w,w).
// Inner loop: 8 LDS.128 + 32 FFMA2 per k-step for 64 MACs (vs 70 slots before).
// ---------------------------------------------------------------------------
#define TM 64
#define TK 16
#define APAD 68

__device__ __forceinline__ void ffma2(ull& d, ull a, ull b) {
    asm("fma.rn.f32x2 %0, %1, %2, %3;" : "=l"(d) : "l"(a), "l"(b), "l"(d));
}

__global__ __launch_bounds__(256) void gemm_kernel(
    const float* __restrict__ Xin,
    const float* __restrict__ W_self,
    const float* __restrict__ W_neigh,
    const float* __restrict__ bias_all,
    float* __restrict__ Yout,
    int layer) {

    const float* __restrict__ X  = (layer == 0) ? Xin : g_h;
    float* __restrict__ Y        = (layer == NLAYERS - 1) ? Yout : g_h;
    const float* __restrict__ Ws = W_self  + (size_t)layer * FF * FF;
    const float* __restrict__ Wn = W_neigh + (size_t)layer * FF * FF;
    const float* __restrict__ bs = bias_all + (size_t)layer * FF;

    __shared__ float As[TK * APAD];
    __shared__ float An[TK * APAD];
    __shared__ float Wsd[TK * 256];   // duplicated: [kk][2c]=(w,w)
    __shared__ float Wnd[TK * 256];

    const int t  = threadIdx.x;
    const int c0 = (t & 31) * 4;        // 4 contiguous output cols
    const int r0 = (t >> 5) * 8;        // 8 contiguous rows (warp-uniform)
    const int m0 = blockIdx.x * TM;
    const int bt = blockIdx.y;

    ull acc2[4][4];                     // [rowpair][col]
    #pragma unroll
    for (int i = 0; i < 4; i++)
        #pragma unroll
        for (int j = 0; j < 4; j++) acc2[i][j] = 0ULL;

    for (int k0 = 0; k0 < FF; k0 += TK) {
        // Weight tiles 16x128, duplicated stores (8 elems/thread/matrix)
        #pragma unroll
        for (int i = 0; i < 8; i++) {
            int idx = t + i * 256;
            int kk = idx >> 7, c = idx & 127;
            float vs = Ws[(size_t)(k0 + kk) * FF + c];
            float vn = Wn[(size_t)(k0 + kk) * FF + c];
            *reinterpret_cast<float2*>(&Wsd[kk * 256 + 2 * c]) = make_float2(vs, vs);
            *reinterpret_cast<float2*>(&Wnd[kk * 256 + 2 * c]) = make_float2(vn, vn);
        }
        // A tiles transposed to k-major (4 elems/thread)
        #pragma unroll
        for (int i = 0; i < 4; i++) {
            int idx = t + i * 256;
            int mm = idx >> 4, kk = idx & 15;
            int row = m0 + mm;
            float xv = 0.0f, av = 0.0f;
            if (row < NN) {
                size_t off = ((size_t)bt * NN + row) * FF + (k0 + kk);
                xv = X[off];
                av = g_agg[off];          // already mean-scaled
            }
            As[kk * APAD + mm] = xv;
            An[kk * APAD + mm] = av;
        }
        __syncthreads();

        #pragma unroll
        for (int kk = 0; kk < TK; kk++) {
            // row pairs: (r0,r0+1),(r0+2,r0+3),(r0+4,r0+5),(r0+6,r0+7)
            ulonglong2 a01 = *reinterpret_cast<const ulonglong2*>(&As[kk * APAD + r0]);
            ulonglong2 a23 = *reinterpret_cast<const ulonglong2*>(&As[kk * APAD + r0 + 4]);
            ulonglong2 n01 = *reinterpret_cast<const ulonglong2*>(&An[kk * APAD + r0]);
            ulonglong2 n23 = *reinterpret_cast<const ulonglong2*>(&An[kk * APAD + r0 + 4]);
            // duplicated W: cols (c0,c0+1) and (c0+2,c0+3)
            ulonglong2 w01 = *reinterpret_cast<const ulonglong2*>(&Wsd[kk * 256 + 2 * c0]);
            ulonglong2 w23 = *reinterpret_cast<const ulonglong2*>(&Wsd[kk * 256 + 2 * c0 + 4]);
            ulonglong2 v01 = *reinterpret_cast<const ulonglong2*>(&Wnd[kk * 256 + 2 * c0]);
            ulonglong2 v23 = *reinterpret_cast<const ulonglong2*>(&Wnd[kk * 256 + 2 * c0 + 4]);

            ull a_[4] = {a01.x, a01.y, a23.x, a23.y};
            ull n_[4] = {n01.x, n01.y, n23.x, n23.y};
            ull ws_[4] = {w01.x, w01.y, w23.x, w23.y};
            ull wn_[4] = {v01.x, v01.y, v23.x, v23.y};

            #pragma unroll
            for (int rp = 0; rp < 4; rp++)
                #pragma unroll
                for (int j = 0; j < 4; j++) {
                    ffma2(acc2[rp][j], a_[rp], ws_[j]);
                    ffma2(acc2[rp][j], n_[rp], wn_[j]);
                }
        }
        __syncthreads();
    }

    // Epilogue: unpack row pairs, add bias, store float4 per row.
    float4 bb = *reinterpret_cast<const float4*>(&bs[c0]);
    #pragma unroll
    for (int rp = 0; rp < 4; rp++) {
        float lo[4], hi[4];
        #pragma unroll
        for (int j = 0; j < 4; j++) {
            lo[j] = __uint_as_float((unsigned int)(acc2[rp][j] & 0xffffffffULL));
            hi[j] = __uint_as_float((unsigned int)(acc2[rp][j] >> 32));
        }
        int row = m0 + r0 + 2 * rp;
        if (row < NN) {
            float4 o = make_float4(lo[0] + bb.x, lo[1] + bb.y,
                                   lo[2] + bb.z, lo[3] + bb.w);
            *reinterpret_cast<float4*>(
                &Y[((size_t)bt * NN + row) * FF + c0]) = o;
        }
        if (row + 1 < NN) {
            float4 o = make_float4(hi[0] + bb.x, hi[1] + bb.y,
                                   hi[2] + bb.z, hi[3] + bb.w);
            *reinterpret_cast<float4*>(
                &Y[((size_t)bt * NN + row + 1) * FF + c0]) = o;
        }
    }
}

// ---------------------------------------------------------------------------
// Launch
// ---------------------------------------------------------------------------
extern "C" void kernel_launch(void* const* d_in, const int* in_sizes, int n_in,
                              void* d_out, int out_size) {
    const float* feature = (const float*)d_in[0];   // [B,T,N,F] == [bt][n][f]
    const float* W_self  = (const float*)d_in[1];   // [L,F,F]
    const float* W_neigh = (const float*)d_in[2];   // [L,F,F]
    const float* bias    = (const float*)d_in[3];   // [L,F]
    const int*   esrc    = (const int*)d_in[4];     // [E]
    const int*   edst    = (const int*)d_in[5];     // [E]
    float* out = (float*)d_out;                     // [B,T,N,F]

    // CSR build (once per call, reused by both layers)
    zero_degi_kernel<<<(NN + 255) / 256, 256>>>();
    degi_kernel<<<(EE + 255) / 256, 256>>>(edst);
    prefix_kernel<<<1, 256>>>();
    fill_kernel<<<(EE + 255) / 256, 256>>>(esrc, edst);

    const int agg_blocks = (NN * 32 + 255) / 256;   // one warp per dst node
    dim3 ggrid((NN + TM - 1) / TM, BT);             // (157, 4)

    for (int layer = 0; layer < NLAYERS; layer++) {
        agg_kernel<<<agg_blocks, 256>>>(feature, layer);
        gemm_kernel<<<ggrid, 256>>>(feature, W_self, W_neigh, bias, out, layer);
    }
}

// round 11
// speedup vs baseline: 1.4211x; 1.4211x over previous
#include <cuda_runtime.h>
#include <cstdint>

#define NN 10000     // nodes
#define FF 128       // feature dim
#define BT 4         // B*T
#define EE 160000    // edges
#define NLAYERS 2

// Persistent device scratch (no allocations in kernel_launch)
__device__ float g_h[(size_t)BT * NN * FF];     // hidden state between layers
__device__ float g_agg[(size_t)BT * NN * FF];   // h_neigh (pre-scaled by 1/deg)
__device__ int   g_degi[NN];
__device__ int   g_rowptr[NN + 1];
__device__ int   g_cursor[NN];
__device__ int   g_csr_src[EE];

typedef unsigned long long ull;

// ---------------------------------------------------------------------------
// CSR build (unchanged — measured cheap: ~20-25us total)
// ---------------------------------------------------------------------------
__global__ void zero_degi_kernel() {
    int i = blockIdx.x * blockDim.x + threadIdx.x;
    if (i < NN) g_degi[i] = 0;
}

__global__ void degi_kernel(const int* __restrict__ edge_dst) {
    int e = blockIdx.x * blockDim.x + threadIdx.x;
    if (e < EE) atomicAdd(&g_degi[edge_dst[e]], 1);
}

__global__ void prefix_kernel() {
    const int CH = 40;                      // 256*40 = 10240 >= NN
    __shared__ int s[256];
    int tid = threadIdx.x;
    int base = tid * CH;
    int local = 0;
    #pragma unroll
    for (int j = 0; j < CH; j++) {
        int idx = base + j;
        if (idx < NN) local += g_degi[idx];
    }
    s[tid] = local;
    __syncthreads();
    if (tid == 0) {
        int run = 0;
        for (int i = 0; i < 256; i++) { int t = s[i]; s[i] = run; run += t; }
    }
    __syncthreads();
    int off = s[tid];
    #pragma unroll
    for (int j = 0; j < CH; j++) {
        int idx = base + j;
        if (idx < NN) {
            g_rowptr[idx] = off;
            g_cursor[idx] = off;
            off += g_degi[idx];
        }
    }
    if (tid == 0) g_rowptr[NN] = EE;
}

__global__ void fill_kernel(const int* __restrict__ edge_src,
                            const int* __restrict__ edge_dst) {
    int e = blockIdx.x * blockDim.x + threadIdx.x;
    if (e < EE) {
        int d = edge_dst[e];
        int p = atomicAdd(&g_cursor[d], 1);
        g_csr_src[p] = edge_src[e];
    }
}

// ---------------------------------------------------------------------------
// Aggregation (unchanged): one warp per dst node, register accumulation.
// ---------------------------------------------------------------------------
__global__ __launch_bounds__(256) void agg_kernel(const float* __restrict__ Xin,
                                                  int layer) {
    const float* __restrict__ X = (layer == 0) ? Xin : g_h;
    int w = (blockIdx.x * blockDim.x + threadIdx.x) >> 5;
    int lane = threadIdx.x & 31;
    if (w >= NN) return;

    int beg = g_rowptr[w];
    int end = g_rowptr[w + 1];
    float inv = (end > beg) ? 1.0f / (float)(end - beg) : 0.0f;

    float4 acc[BT];
    #pragma unroll
    for (int bt = 0; bt < BT; bt++) acc[bt] = make_float4(0.f, 0.f, 0.f, 0.f);

    int e = beg;
    for (; e + 1 < end; e += 2) {
        int s0 = g_csr_src[e];
        int s1 = g_csr_src[e + 1];
        #pragma unroll
        for (int bt = 0; bt < BT; bt++) {
            float4 v0 = *reinterpret_cast<const float4*>(
                X + ((size_t)bt * NN + s0) * FF + lane * 4);
            float4 v1 = *reinterpret_cast<const float4*>(
                X + ((size_t)bt * NN + s1) * FF + lane * 4);
            acc[bt].x += v0.x + v1.x;
            acc[bt].y += v0.y + v1.y;
            acc[bt].z += v0.z + v1.z;
            acc[bt].w += v0.w + v1.w;
        }
    }
    if (e < end) {
        int s0 = g_csr_src[e];
        #pragma unroll
        for (int bt = 0; bt < BT; bt++) {
            float4 v0 = *reinterpret_cast<const float4*>(
                X + ((size_t)bt * NN + s0) * FF + lane * 4);
            acc[bt].x += v0.x; acc[bt].y += v0.y;
            acc[bt].z += v0.z; acc[bt].w += v0.w;
        }
    }
    #pragma unroll
    for (int bt = 0; bt < BT; bt++) {
        float4 o;
        o.x = acc[bt].x * inv; o.y = acc[bt].y * inv;
        o.z = acc[bt].z * inv; o.w = acc[bt].w * inv;
        *reinterpret_cast<float4*>(
            g_agg + ((size_t)bt * NN + w) * FF + lane * 4) = o;
    }
}

// ---------------------------------------------------------------------------
// GEMM v2 — crossbar-optimized:
//   Y = X*Ws + Agg*Wn + b
// R10 showed the old FFMA2 gemm was smem-crossbar-bound (2 B/MAC from the
// duplicated-W tiles). v2: thread tile 16 rows x 4 cols (acc in 32 f32x2),
// W stored NON-duplicated in smem (1 LDS.128/matrix/k-step, conflict-free)
// and duplicated into (w,w) pairs via mov.b64 in registers.
// Per k-step: 10 LDS + 8 MOV + 64 FFMA2 per 128 MACs -> 1.25 B/MAC.
// smem 16.6 KB -> 2 CTA/SM; 316 blocks -> ~1.07 waves.
// ---------------------------------------------------------------------------
#define TM2 128
#define TK2 8
#define APAD2 132   // 132*4 = 528 B row stride, 16B-divisible; banks offset 4/row

__device__ __forceinline__ void ffma2(ull& d, ull a, ull b) {
    asm("fma.rn.f32x2 %0, %1, %2, %3;" : "=l"(d) : "l"(a), "l"(b), "l"(d));
}
__device__ __forceinline__ ull dup2(float x) {
    ull d;
    asm("mov.b64 %0, {%1, %1};" : "=l"(d) : "f"(x));
    return d;
}

__global__ __launch_bounds__(256, 2) void gemm_kernel(
    const float* __restrict__ Xin,
    const float* __restrict__ W_self,
    const float* __restrict__ W_neigh,
    const float* __restrict__ bias_all,
    float* __restrict__ Yout,
    int layer) {

    const float* __restrict__ X  = (layer == 0) ? Xin : g_h;
    float* __restrict__ Y        = (layer == NLAYERS - 1) ? Yout : g_h;
    const float* __restrict__ Ws = W_self  + (size_t)layer * FF * FF;
    const float* __restrict__ Wn = W_neigh + (size_t)layer * FF * FF;
    const float* __restrict__ bs = bias_all + (size_t)layer * FF;

    __shared__ float As[TK2 * APAD2];     // k-major: [kk][row]
    __shared__ float An[TK2 * APAD2];
    __shared__ float Wss[TK2 * FF];       // [kk][col], non-duplicated
    __shared__ float Wns[TK2 * FF];

    const int t  = threadIdx.x;
    const int c0 = (t & 31) * 4;          // 4 contiguous output cols per thread
    const int r0 = (t >> 5) * 16;         // 16 rows per thread (warp-uniform)
    const int m0 = blockIdx.x * TM2;
    const int bt = blockIdx.y;

    // A-tile load mapping: 2 threads per row, 4 consecutive k each (LDG.128)
    const int lrow = t >> 1;              // 0..127
    const int lk   = (t & 1) * 4;         // 0 or 4
    // W-tile load mapping: 32 threads per k-row, 4 cols each (LDG.128)
    const int wkk  = t >> 5;              // 0..7
    const int wc   = (t & 31) * 4;        // 0..124

    ull acc[8][4];                        // [rowpair][col]
    #pragma unroll
    for (int i = 0; i < 8; i++)
        #pragma unroll
        for (int j = 0; j < 4; j++) acc[i][j] = 0ULL;

    for (int k0 = 0; k0 < FF; k0 += TK2) {
        // --- A tiles: transpose to k-major. 1 LDG.128 per matrix per thread.
        {
            int grow = m0 + lrow;
            float4 xv = make_float4(0.f, 0.f, 0.f, 0.f);
            float4 av = make_float4(0.f, 0.f, 0.f, 0.f);
            if (grow < NN) {
                size_t off = ((size_t)bt * NN + grow) * FF + (k0 + lk);
                xv = *reinterpret_cast<const float4*>(X + off);
                av = *reinterpret_cast<const float4*>(g_agg + off);
            }
            As[(lk + 0) * APAD2 + lrow] = xv.x;
            As[(lk + 1) * APAD2 + lrow] = xv.y;
            As[(lk + 2) * APAD2 + lrow] = xv.z;
            As[(lk + 3) * APAD2 + lrow] = xv.w;
            An[(lk + 0) * APAD2 + lrow] = av.x;
            An[(lk + 1) * APAD2 + lrow] = av.y;
            An[(lk + 2) * APAD2 + lrow] = av.z;
            An[(lk + 3) * APAD2 + lrow] = av.w;
        }
        // --- W tiles: 1 LDG.128 + 1 STS.128 per matrix per thread, coalesced.
        {
            size_t woff = (size_t)(k0 + wkk) * FF + wc;
            *reinterpret_cast<float4*>(&Wss[wkk * FF + wc]) =
                *reinterpret_cast<const float4*>(Ws + woff);
            *reinterpret_cast<float4*>(&Wns[wkk * FF + wc]) =
                *reinterpret_cast<const float4*>(Wn + woff);
        }
        __syncthreads();

        #pragma unroll
        for (int kk = 0; kk < TK2; kk++) {
            // ---- self term
            {
                float4 w = *reinterpret_cast<const float4*>(&Wss[kk * FF + c0]);
                ull w2[4] = {dup2(w.x), dup2(w.y), dup2(w.z), dup2(w.w)};
                ulonglong2 A01 = *reinterpret_cast<const ulonglong2*>(&As[kk * APAD2 + r0]);
                ulonglong2 A23 = *reinterpret_cast<const ulonglong2*>(&As[kk * APAD2 + r0 + 4]);
                ulonglong2 A45 = *reinterpret_cast<const ulonglong2*>(&As[kk * APAD2 + r0 + 8]);
                ulonglong2 A67 = *reinterpret_cast<const ulonglong2*>(&As[kk * APAD2 + r0 + 12]);
                ull a_[8] = {A01.x, A01.y, A23.x, A23.y, A45.x, A45.y, A67.x, A67.y};
                #pragma unroll
                for (int rp = 0; rp < 8; rp++)
                    #pragma unroll
                    for (int j = 0; j < 4; j++)
                        ffma2(acc[rp][j], a_[rp], w2[j]);
            }
            // ---- neighbor term
            {
                float4 w = *reinterpret_cast<const float4*>(&Wns[kk * FF + c0]);
                ull w2[4] = {dup2(w.x), dup2(w.y), dup2(w.z), dup2(w.w)};
                ulonglong2 A01 = *reinterpret_cast<const ulonglong2*>(&An[kk * APAD2 + r0]);
                ulonglong2 A23 = *reinterpret_cast<const ulonglong2*>(&An[kk * APAD2 + r0 + 4]);
                ulonglong2 A45 = *reinterpret_cast<const ulonglong2*>(&An[kk * APAD2 + r0 + 8]);
                ulonglong2 A67 = *reinterpret_cast<const ulonglong2*>(&An[kk * APAD2 + r0 + 12]);
                ull a_[8] = {A01.x, A01.y, A23.x, A23.y, A45.x, A45.y, A67.x, A67.y};
                #pragma unroll
                for (int rp = 0; rp < 8; rp++)
                    #pragma unroll
                    for (int j = 0; j < 4; j++)
                        ffma2(acc[rp][j], a_[rp], w2[j]);
            }
        }
        __syncthreads();
    }

    // Epilogue: unpack row pairs, add bias, store float4 per row.
    float4 bb = *reinterpret_cast<const float4*>(&bs[c0]);
    #pragma unroll
    for (int rp = 0; rp < 8; rp++) {
        float lo[4], hi[4];
        #pragma unroll
        for (int j = 0; j < 4; j++) {
            lo[j] = __uint_as_float((unsigned int)(acc[rp][j] & 0xffffffffULL));
            hi[j] = __uint_as_float((unsigned int)(acc[rp][j] >> 32));
        }
        int row = m0 + r0 + 2 * rp;
        if (row < NN) {
            float4 o = make_float4(lo[0] + bb.x, lo[1] + bb.y,
                                   lo[2] + bb.z, lo[3] + bb.w);
            *reinterpret_cast<float4*>(
                &Y[((size_t)bt * NN + row) * FF + c0]) = o;
        }
        if (row + 1 < NN) {
            float4 o = make_float4(hi[0] + bb.x, hi[1] + bb.y,
                                   hi[2] + bb.z, hi[3] + bb.w);
            *reinterpret_cast<float4*>(
                &Y[((size_t)bt * NN + row + 1) * FF + c0]) = o;
        }
    }
}

// ---------------------------------------------------------------------------
// Launch
// ---------------------------------------------------------------------------
extern "C" void kernel_launch(void* const* d_in, const int* in_sizes, int n_in,
                              void* d_out, int out_size) {
    const float* feature = (const float*)d_in[0];   // [B,T,N,F] == [bt][n][f]
    const float* W_self  = (const float*)d_in[1];   // [L,F,F]
    const float* W_neigh = (const float*)d_in[2];   // [L,F,F]
    const float* bias    = (const float*)d_in[3];   // [L,F]
    const int*   esrc    = (const int*)d_in[4];     // [E]
    const int*   edst    = (const int*)d_in[5];     // [E]
    float* out = (float*)d_out;                     // [B,T,N,F]

    // CSR build (once per call, reused by both layers)
    zero_degi_kernel<<<(NN + 255) / 256, 256>>>();
    degi_kernel<<<(EE + 255) / 256, 256>>>(edst);
    prefix_kernel<<<1, 256>>>();
    fill_kernel<<<(EE + 255) / 256, 256>>>(esrc, edst);

    const int agg_blocks = (NN * 32 + 255) / 256;   // one warp per dst node
    dim3 ggrid((NN + TM2 - 1) / TM2, BT);           // (79, 4) = 316 blocks

    for (int layer = 0; layer < NLAYERS; layer++) {
        agg_kernel<<<agg_blocks, 256>>>(feature, layer);
        gemm_kernel<<<ggrid, 256>>>(feature, W_self, W_neigh, bias, out, layer);
    }
}

// round 15
// speedup vs baseline: 1.4991x; 1.0549x over previous
#include <cuda_runtime.h>
#include <cstdint>

#define NN 10000     // nodes
#define FF 128       // feature dim
#define BT 4         // B*T
#define EE 160000    // edges
#define NLAYERS 2

// Persistent device scratch (no allocations in kernel_launch)
__device__ float g_h[(size_t)BT * NN * FF];     // hidden state between layers
__device__ float g_agg[(size_t)BT * NN * FF];   // h_neigh (pre-scaled by 1/deg)
__device__ int   g_degi[NN];
__device__ int   g_rowptr[NN + 1];
__device__ int   g_cursor[NN];
__device__ int   g_csr_src[EE];

typedef unsigned long long ull;

// ---------------------------------------------------------------------------
// CSR build (measured cheap; unchanged)
// ---------------------------------------------------------------------------
__global__ void zero_degi_kernel() {
    int i = blockIdx.x * blockDim.x + threadIdx.x;
    if (i < NN) g_degi[i] = 0;
}

__global__ void degi_kernel(const int* __restrict__ edge_dst) {
    int e = blockIdx.x * blockDim.x + threadIdx.x;
    if (e < EE) atomicAdd(&g_degi[edge_dst[e]], 1);
}

__global__ void prefix_kernel() {
    const int CH = 40;                      // 256*40 = 10240 >= NN
    __shared__ int s[256];
    int tid = threadIdx.x;
    int base = tid * CH;
    int local = 0;
    #pragma unroll
    for (int j = 0; j < CH; j++) {
        int idx = base + j;
        if (idx < NN) local += g_degi[idx];
    }
    s[tid] = local;
    __syncthreads();
    if (tid == 0) {
        int run = 0;
        for (int i = 0; i < 256; i++) { int t = s[i]; s[i] = run; run += t; }
    }
    __syncthreads();
    int off = s[tid];
    #pragma unroll
    for (int j = 0; j < CH; j++) {
        int idx = base + j;
        if (idx < NN) {
            g_rowptr[idx] = off;
            g_cursor[idx] = off;
            off += g_degi[idx];
        }
    }
    if (tid == 0) g_rowptr[NN] = EE;
}

__global__ void fill_kernel(const int* __restrict__ edge_src,
                            const int* __restrict__ edge_dst) {
    int e = blockIdx.x * blockDim.x + threadIdx.x;
    if (e < EE) {
        int d = edge_dst[e];
        int p = atomicAdd(&g_cursor[d], 1);
        g_csr_src[p] = edge_src[e];
    }
}

// ---------------------------------------------------------------------------
// Aggregation (unchanged): one warp per dst node, register accumulation.
// ---------------------------------------------------------------------------
__global__ __launch_bounds__(256) void agg_kernel(const float* __restrict__ Xin,
                                                  int layer) {
    const float* __restrict__ X = (layer == 0) ? Xin : g_h;
    int w = (blockIdx.x * blockDim.x + threadIdx.x) >> 5;
    int lane = threadIdx.x & 31;
    if (w >= NN) return;

    int beg = g_rowptr[w];
    int end = g_rowptr[w + 1];
    float inv = (end > beg) ? 1.0f / (float)(end - beg) : 0.0f;

    float4 acc[BT];
    #pragma unroll
    for (int bt = 0; bt < BT; bt++) acc[bt] = make_float4(0.f, 0.f, 0.f, 0.f);

    int e = beg;
    for (; e + 1 < end; e += 2) {
        int s0 = g_csr_src[e];
        int s1 = g_csr_src[e + 1];
        #pragma unroll
        for (int bt = 0; bt < BT; bt++) {
            float4 v0 = *reinterpret_cast<const float4*>(
                X + ((size_t)bt * NN + s0) * FF + lane * 4);
            float4 v1 = *reinterpret_cast<const float4*>(
                X + ((size_t)bt * NN + s1) * FF + lane * 4);
            acc[bt].x += v0.x + v1.x;
            acc[bt].y += v0.y + v1.y;
            acc[bt].z += v0.z + v1.z;
            acc[bt].w += v0.w + v1.w;
        }
    }
    if (e < end) {
        int s0 = g_csr_src[e];
        #pragma unroll
        for (int bt = 0; bt < BT; bt++) {
            float4 v0 = *reinterpret_cast<const float4*>(
                X + ((size_t)bt * NN + s0) * FF + lane * 4);
            acc[bt].x += v0.x; acc[bt].y += v0.y;
            acc[bt].z += v0.z; acc[bt].w += v0.w;
        }
    }
    #pragma unroll
    for (int bt = 0; bt < BT; bt++) {
        float4 o;
        o.x = acc[bt].x * inv; o.y = acc[bt].y * inv;
        o.z = acc[bt].z * inv; o.w = acc[bt].w * inv;
        *reinterpret_cast<float4*>(
            g_agg + ((size_t)bt * NN + w) * FF + lane * 4) = o;
    }
}

// ---------------------------------------------------------------------------
// GEMM v3 — v2 + double-buffered k0 loop (register prefetch):
// R11 showed v2 at ~60-65us/layer vs a 39us FFMA2-pipe floor; the gap is
// exposed LDG latency (load->sync->compute each k0 iter). v3 issues the next
// tile's LDGs right after the barrier so ~600cyc of latency hides under the
// 8-kk compute block. Prefetch = 16 regs/thread; still 2 CTA/SM.
// ---------------------------------------------------------------------------
#define TM2 128
#define TK2 8
#define APAD2 132   // 132*4 = 528 B row stride, 16B-divisible

__device__ __forceinline__ void ffma2(ull& d, ull a, ull b) {
    asm("fma.rn.f32x2 %0, %1, %2, %3;" : "=l"(d) : "l"(a), "l"(b), "l"(d));
}
__device__ __forceinline__ ull dup2(float x) {
    ull d;
    asm("mov.b64 %0, {%1, %1};" : "=l"(d) : "f"(x));
    return d;
}

__global__ __launch_bounds__(256, 2) void gemm_kernel(
    const float* __restrict__ Xin,
    const float* __restrict__ W_self,
    const float* __restrict__ W_neigh,
    const float* __restrict__ bias_all,
    float* __restrict__ Yout,
    int layer) {

    const float* __restrict__ X  = (layer == 0) ? Xin : g_h;
    float* __restrict__ Y        = (layer == NLAYERS - 1) ? Yout : g_h;
    const float* __restrict__ Ws = W_self  + (size_t)layer * FF * FF;
    const float* __restrict__ Wn = W_neigh + (size_t)layer * FF * FF;
    const float* __restrict__ bs = bias_all + (size_t)layer * FF;

    __shared__ float As[TK2 * APAD2];     // k-major: [kk][row]
    __shared__ float An[TK2 * APAD2];
    __shared__ float Wss[TK2 * FF];       // [kk][col]
    __shared__ float Wns[TK2 * FF];

    const int t  = threadIdx.x;
    const int c0 = (t & 31) * 4;          // 4 contiguous output cols
    const int r0 = (t >> 5) * 16;         // 16 rows (warp-uniform -> LDS broadcast)
    const int m0 = blockIdx.x * TM2;
    const int bt = blockIdx.y;

    // A-tile load mapping: 2 threads per row, 4 consecutive k each
    const int lrow = t >> 1;              // 0..127
    const int lk   = (t & 1) * 4;         // 0 or 4
    // W-tile load mapping: 32 threads per k-row, 4 cols each
    const int wkk  = t >> 5;              // 0..7
    const int wc   = (t & 31) * 4;        // 0..124

    const int  grow   = m0 + lrow;
    const bool rowok  = (grow < NN);
    const size_t abase = ((size_t)bt * NN + grow) * FF + lk;

    ull acc[8][4];
    #pragma unroll
    for (int i = 0; i < 8; i++)
        #pragma unroll
        for (int j = 0; j < 4; j++) acc[i][j] = 0ULL;

    // ---- prologue: prefetch tile k0=0 into registers
    float4 xv = make_float4(0.f, 0.f, 0.f, 0.f);
    float4 av = make_float4(0.f, 0.f, 0.f, 0.f);
    if (rowok) {
        xv = *reinterpret_cast<const float4*>(X + abase);
        av = *reinterpret_cast<const float4*>(g_agg + abase);
    }
    float4 wsv = *reinterpret_cast<const float4*>(Ws + (size_t)wkk * FF + wc);
    float4 wnv = *reinterpret_cast<const float4*>(Wn + (size_t)wkk * FF + wc);

    for (int k0 = 0; k0 < FF; k0 += TK2) {
        // ---- stage current tile from regs into smem
        As[(lk + 0) * APAD2 + lrow] = xv.x;
        As[(lk + 1) * APAD2 + lrow] = xv.y;
        As[(lk + 2) * APAD2 + lrow] = xv.z;
        As[(lk + 3) * APAD2 + lrow] = xv.w;
        An[(lk + 0) * APAD2 + lrow] = av.x;
        An[(lk + 1) * APAD2 + lrow] = av.y;
        An[(lk + 2) * APAD2 + lrow] = av.z;
        An[(lk + 3) * APAD2 + lrow] = av.w;
        *reinterpret_cast<float4*>(&Wss[wkk * FF + wc]) = wsv;
        *reinterpret_cast<float4*>(&Wns[wkk * FF + wc]) = wnv;
        __syncthreads();

        // ---- issue next tile's LDGs (latency hides under compute below)
        int kn = k0 + TK2;
        if (kn < FF) {
            if (rowok) {
                xv = *reinterpret_cast<const float4*>(X + abase + kn);
                av = *reinterpret_cast<const float4*>(g_agg + abase + kn);
            }
            wsv = *reinterpret_cast<const float4*>(Ws + (size_t)(kn + wkk) * FF + wc);
            wnv = *reinterpret_cast<const float4*>(Wn + (size_t)(kn + wkk) * FF + wc);
        }

        // ---- compute 8 kk steps
        #pragma unroll
        for (int kk = 0; kk < TK2; kk++) {
            {   // self term
                float4 w = *reinterpret_cast<const float4*>(&Wss[kk * FF + c0]);
                ull w2[4] = {dup2(w.x), dup2(w.y), dup2(w.z), dup2(w.w)};
                ulonglong2 A01 = *reinterpret_cast<const ulonglong2*>(&As[kk * APAD2 + r0]);
                ulonglong2 A23 = *reinterpret_cast<const ulonglong2*>(&As[kk * APAD2 + r0 + 4]);
                ulonglong2 A45 = *reinterpret_cast<const ulonglong2*>(&As[kk * APAD2 + r0 + 8]);
                ulonglong2 A67 = *reinterpret_cast<const ulonglong2*>(&As[kk * APAD2 + r0 + 12]);
                ull a_[8] = {A01.x, A01.y, A23.x, A23.y, A45.x, A45.y, A67.x, A67.y};
                #pragma unroll
                for (int rp = 0; rp < 8; rp++)
                    #pragma unroll
                    for (int j = 0; j < 4; j++)
                        ffma2(acc[rp][j], a_[rp], w2[j]);
            }
            {   // neighbor term
                float4 w = *reinterpret_cast<const float4*>(&Wns[kk * FF + c0]);
                ull w2[4] = {dup2(w.x), dup2(w.y), dup2(w.z), dup2(w.w)};
                ulonglong2 A01 = *reinterpret_cast<const ulonglong2*>(&An[kk * APAD2 + r0]);
                ulonglong2 A23 = *reinterpret_cast<const ulonglong2*>(&An[kk * APAD2 + r0 + 4]);
                ulonglong2 A45 = *reinterpret_cast<const ulonglong2*>(&An[kk * APAD2 + r0 + 8]);
                ulonglong2 A67 = *reinterpret_cast<const ulonglong2*>(&An[kk * APAD2 + r0 + 12]);
                ull a_[8] = {A01.x, A01.y, A23.x, A23.y, A45.x, A45.y, A67.x, A67.y};
                #pragma unroll
                for (int rp = 0; rp < 8; rp++)
                    #pragma unroll
                    for (int j = 0; j < 4; j++)
                        ffma2(acc[rp][j], a_[rp], w2[j]);
            }
        }
        __syncthreads();
    }

    // Epilogue: unpack row pairs, add bias, store float4 per row.
    float4 bb = *reinterpret_cast<const float4*>(&bs[c0]);
    #pragma unroll
    for (int rp = 0; rp < 8; rp++) {
        float lo[4], hi[4];
        #pragma unroll
        for (int j = 0; j < 4; j++) {
            lo[j] = __uint_as_float((unsigned int)(acc[rp][j] & 0xffffffffULL));
            hi[j] = __uint_as_float((unsigned int)(acc[rp][j] >> 32));
        }
        int row = m0 + r0 + 2 * rp;
        if (row < NN) {
            float4 o = make_float4(lo[0] + bb.x, lo[1] + bb.y,
                                   lo[2] + bb.z, lo[3] + bb.w);
            *reinterpret_cast<float4*>(
                &Y[((size_t)bt * NN + row) * FF + c0]) = o;
        }
        if (row + 1 < NN) {
            float4 o = make_float4(hi[0] + bb.x, hi[1] + bb.y,
                                   hi[2] + bb.z, hi[3] + bb.w);
            *reinterpret_cast<float4*>(
                &Y[((size_t)bt * NN + row + 1) * FF + c0]) = o;
        }
    }
}

// ---------------------------------------------------------------------------
// Launch
// ---------------------------------------------------------------------------
extern "C" void kernel_launch(void* const* d_in, const int* in_sizes, int n_in,
                              void* d_out, int out_size) {
    const float* feature = (const float*)d_in[0];   // [B,T,N,F] == [bt][n][f]
    const float* W_self  = (const float*)d_in[1];   // [L,F,F]
    const float* W_neigh = (const float*)d_in[2];   // [L,F,F]
    const float* bias    = (const float*)d_in[3];   // [L,F]
    const int*   esrc    = (const int*)d_in[4];     // [E]
    const int*   edst    = (const int*)d_in[5];     // [E]
    float* out = (float*)d_out;                     // [B,T,N,F]

    // CSR build (once per call, reused by both layers)
    zero_degi_kernel<<<(NN + 255) / 256, 256>>>();
    degi_kernel<<<(EE + 255) / 256, 256>>>(edst);
    prefix_kernel<<<1, 256>>>();
    fill_kernel<<<(EE + 255) / 256, 256>>>(esrc, edst);

    const int agg_blocks = (NN * 32 + 255) / 256;   // one warp per dst node
    dim3 ggrid((NN + TM2 - 1) / TM2, BT);           // (79, 4) = 316 blocks

    for (int layer = 0; layer < NLAYERS; layer++) {
        agg_kernel<<<agg_blocks, 256>>>(feature, layer);
        gemm_kernel<<<ggrid, 256>>>(feature, W_self, W_neigh, bias, out, layer);
    }
}